// round 1
// baseline (speedup 1.0000x reference)
#include <cuda_runtime.h>

#define NBATCH 64
#define NPTS   4096      // H*W
#define NC     128
#define NV4    (NC / 4)  // 32 float4 per point
#define NWARPS 32
#define PPW    (NPTS / NWARPS)  // 128 points per warp

// per-point stashed scalars: {alpha, s, c, t2}; 64*4096*16B = 4MB
__device__ float4 g_scr[NBATCH * NPTS];

__device__ __forceinline__ float dot4(float4 a, float4 b) {
    return a.x * b.x + a.y * b.y + a.z * b.z + a.w * b.w;
}

__device__ __forceinline__ float warpsum(float v) {
    v += __shfl_xor_sync(0xffffffffu, v, 16);
    v += __shfl_xor_sync(0xffffffffu, v, 8);
    v += __shfl_xor_sync(0xffffffffu, v, 4);
    v += __shfl_xor_sync(0xffffffffu, v, 2);
    v += __shfl_xor_sync(0xffffffffu, v, 1);
    return v;
}

__global__ __launch_bounds__(1024, 1)
void lbn_kernel(const float* __restrict__ x,
                const float* __restrict__ beta,
                const float* __restrict__ gamma,
                float* __restrict__ out) {
    const int b    = blockIdx.x;
    const int tid  = threadIdx.x;
    const int warp = tid >> 5;
    const int lane = tid & 31;

    const float4* __restrict__ xb = (const float4*)x + (size_t)b * NPTS * NV4;
    float4* __restrict__ ob       = (float4*)out + (size_t)b * NPTS * NV4;
    float4* scr                   = g_scr + (size_t)b * NPTS;

    __shared__ float4 s_red[NWARPS * 32];  // 16 KB
    __shared__ float4 s_mean[32];
    __shared__ float  s_sc[8];
    __shared__ float  s_w[NWARPS];

    const float4 beta4 = ((const float4*)beta)[lane];
    const int base = warp * PPW;

    // ---------------- Pass 1: per-channel mean over the batch ----------------
    float4 acc = make_float4(0.f, 0.f, 0.f, 0.f);
    for (int k = 0; k < PPW; ++k) {
        float4 v = xb[(base + k) * NV4 + lane];
        acc.x += v.x; acc.y += v.y; acc.z += v.z; acc.w += v.w;
    }
    s_red[tid] = acc;
    __syncthreads();
    for (int s = 16; s > 0; s >>= 1) {
        if (warp < s) {
            float4 a = s_red[tid];
            float4 c = s_red[tid + s * 32];
            a.x += c.x; a.y += c.y; a.z += c.z; a.w += c.w;
            s_red[tid] = a;
        }
        __syncthreads();
    }

    if (warp == 0) {
        float4 m = s_red[lane];
        const float invN = 1.0f / NPTS;
        m.x *= invN; m.y *= invN; m.z *= invN; m.w *= invN;
        float d     = warpsum(dot4(m, m));
        float m0raw = __shfl_sync(0xffffffffu, m.x, 0);
        // -linner(m,m) = 2*m0^2 - dot(m,m); clip at 1e-8
        float denom = fmaxf(2.f * m0raw * m0raw - d, 1e-8f);
        float inv   = rsqrtf(denom);
        float4 mean = make_float4(m.x * inv, m.y * inv, m.z * inv, m.w * inv);
        s_mean[lane] = mean;
        float bb = warpsum(dot4(beta4, beta4));
        if (lane == 0) {
            float mean0 = m0raw * inv;
            s_sc[0] = mean0;
            s_sc[1] = 1.f / (1.f + mean0);
            float b0 = beta4.x;            // channel 0 lives in lane 0
            s_sc[2] = b0;
            s_sc[3] = 1.f / (1.f + b0);
            s_sc[4] = bb + 2.f * b0 + 1.f; // dot(beta+e0, beta+e0)
        }
    }
    __syncthreads();

    const float4 mean4 = s_mean[lane];
    const float  mean0 = s_sc[0];
    const float  i1m   = s_sc[1];

    float4 em = mean4;   // mean + e0 (lane-local view)
    float4 be = beta4;   // beta + e0
    if (lane == 0) { em.x += 1.f; be.x += 1.f; }

    // ---------------- Pass 2: tangent vectors at origin; Frechet variance ----
    float nacc = 0.f;
    for (int k = 0; k < PPW; ++k) {
        const int p = base + k;
        float4 v = xb[p * NV4 + lane];

        float dxm = warpsum(dot4(v, mean4));
        float x0  = __shfl_sync(0xffffffffu, v.x, 0);
        // alpha = -linner(mean,x) = 2*mean0*x0 - dot(mean,x), clip >= 1+1e-7
        float alpha = fmaxf(2.f * mean0 * x0 - dxm, 1.f + 1e-7f);

        float4 u;
        u.x = v.x - alpha * mean4.x;
        u.y = v.y - alpha * mean4.y;
        u.z = v.z - alpha * mean4.z;
        u.w = v.w - alpha * mean4.w;

        float duu = warpsum(dot4(u, u));
        float u0  = __shfl_sync(0xffffffffu, u.x, 0);
        float luu = fmaxf(duu - 2.f * u0 * u0, 1e-8f);  // linner(u,u), clipped
        float un  = sqrtf(luu);
        float s   = acoshf(alpha) / un;                 // x_T = s*u
        float c   = s * u0 * i1m;                       // PT mean->origin coeff

        float4 t;  // x_T after transport to origin
        t.x = s * u.x - c * em.x;
        t.y = s * u.y - c * em.y;
        t.z = s * u.z - c * em.z;
        t.w = s * u.w - c * em.w;
        float t2 = warpsum(dot4(t, t));
        nacc += sqrtf(t2);

        if (lane == 0) scr[p] = make_float4(alpha, s, c, t2);
    }
    if (lane == 0) s_w[warp] = nacc;
    __syncthreads();
    if (warp == 0) {
        float tot = warpsum(s_w[lane]);
        if (lane == 0) {
            float var = tot / NPTS;
            s_sc[5] = gamma[0] / (var + 1e-5f);
        }
    }
    __syncthreads();

    const float g   = s_sc[5];
    const float b0  = s_sc[2];
    const float i1b = s_sc[3];
    const float nbb = s_sc[4];

    // ---------------- Pass 3: scale, transport to beta, expmap, write --------
    for (int k = 0; k < PPW; ++k) {
        const int p = base + k;
        float4 v  = xb[p * NV4 + lane];
        float4 sc = scr[p];  // broadcast load
        const float alpha = sc.x, s = sc.y, c = sc.z, t2 = sc.w;

        float4 y;  // y = g * x_T'
        y.x = g * (s * (v.x - alpha * mean4.x) - c * em.x);
        y.y = g * (s * (v.y - alpha * mean4.y) - c * em.y);
        y.z = g * (s * (v.z - alpha * mean4.z) - c * em.z);
        y.w = g * (s * (v.w - alpha * mean4.w) - c * em.w);

        float dby = warpsum(dot4(beta4, y));
        float y0  = __shfl_sync(0xffffffffu, y.x, 0);
        // pt = linner(beta, y) / (1 + beta0)
        float pt = (dby - 2.f * b0 * y0) * i1b;

        float4 f;  // x_T_final = y + pt*(beta + e0)
        f.x = y.x + pt * be.x;
        f.y = y.y + pt * be.y;
        f.z = y.z + pt * be.z;
        f.w = y.w + pt * be.w;

        // dot(f,f) analytically: dot(y,y)=g^2*t2, dot(y,beta+e0)=dby+y0
        float dff = g * g * t2 + 2.f * pt * (dby + y0) + pt * pt * nbb;
        float f0  = y0 + pt * (b0 + 1.f);
        float lf  = fmaxf(dff - 2.f * f0 * f0, 1e-8f);  // linner(f,f), clipped
        float nu  = sqrtf(lf);
        float ch  = coshf(nu);
        float sh  = sinhf(nu) / nu;

        float4 o;
        o.x = ch * beta4.x + sh * f.x;
        o.y = ch * beta4.y + sh * f.y;
        o.z = ch * beta4.z + sh * f.z;
        o.w = ch * beta4.w + sh * f.w;
        ob[p * NV4 + lane] = o;
    }
}

extern "C" void kernel_launch(void* const* d_in, const int* in_sizes, int n_in,
                              void* d_out, int out_size) {
    const float* x     = (const float*)d_in[0];
    const float* beta  = (const float*)d_in[1];
    const float* gamma = (const float*)d_in[2];
    float* out = (float*)d_out;
    lbn_kernel<<<NBATCH, 1024>>>(x, beta, gamma, out);
}

// round 5
// speedup vs baseline: 1.8245x; 1.8245x over previous
#include <cuda_runtime.h>

#define NBATCH 64
#define NPTS   4096
#define NV4    32          // 128 channels = 32 float4
#define NSL    16          // slices per batch
#define PPS    (NPTS / NSL)        // 256 points per slice/CTA
#define PPWARP 32                  // points per warp (8 warps/CTA)

// scratch (device globals; no allocation)
__device__ float4 g_part [NBATCH * NSL * NV4];   // per-slice channel sums
__device__ float4 g_mean [NBATCH * NV4];         // projected centroid
__device__ float  g_sc   [NBATCH * 16];          // per-batch scalars
__device__ float4 g_scr4 [NBATCH * NPTS];        // {s, s*alpha, c, t2}
__device__ float  g_scrd [NBATCH * NPTS];        // dot(beta, x_T)
__device__ float  g_vpart[NBATCH * NSL];         // per-slice sum of ||x_T||

__device__ __forceinline__ float dot4(float4 a, float4 b) {
    return a.x * b.x + a.y * b.y + a.z * b.z + a.w * b.w;
}
__device__ __forceinline__ float warpsum(float v) {
    #pragma unroll
    for (int o = 16; o > 0; o >>= 1) v += __shfl_xor_sync(0xffffffffu, v, o);
    return v;
}
// three independent butterflies, interleaved for ILP
__device__ __forceinline__ void warpsum3(float& a, float& b, float& c) {
    #pragma unroll
    for (int o = 16; o > 0; o >>= 1) {
        a += __shfl_xor_sync(0xffffffffu, a, o);
        b += __shfl_xor_sync(0xffffffffu, b, o);
        c += __shfl_xor_sync(0xffffffffu, c, o);
    }
}

// ---------------- K1: per-slice channel sums ----------------
__global__ __launch_bounds__(256)
void k1_sums(const float* __restrict__ x) {
    const int blk = blockIdx.x, b = blk >> 4, sl = blk & 15;
    const int warp = threadIdx.x >> 5, lane = threadIdx.x & 31;
    const float4* __restrict__ xb = (const float4*)x + (size_t)b * NPTS * NV4;
    const int base = sl * PPS + warp * PPWARP;

    float4 acc = make_float4(0.f, 0.f, 0.f, 0.f);
    #pragma unroll 4
    for (int k = 0; k < PPWARP; ++k) {
        float4 v = xb[(size_t)(base + k) * NV4 + lane];
        acc.x += v.x; acc.y += v.y; acc.z += v.z; acc.w += v.w;
    }
    __shared__ float4 sr[256];
    sr[threadIdx.x] = acc;
    __syncthreads();
    #pragma unroll
    for (int off = 128; off >= 32; off >>= 1) {
        if (threadIdx.x < off) {
            float4 a = sr[threadIdx.x], c = sr[threadIdx.x + off];
            a.x += c.x; a.y += c.y; a.z += c.z; a.w += c.w;
            sr[threadIdx.x] = a;
        }
        __syncthreads();
    }
    if (threadIdx.x < 32) g_part[blk * NV4 + lane] = sr[lane];
}

// ---------------- K2: mean + per-batch scalars ----------------
__global__ __launch_bounds__(32)
void k2_mean(const float* __restrict__ beta) {
    const int b = blockIdx.x, lane = threadIdx.x;
    const float4 beta4 = ((const float4*)beta)[lane];

    float4 m = make_float4(0.f, 0.f, 0.f, 0.f);
    for (int s = 0; s < NSL; ++s) {
        float4 p = g_part[(b * NSL + s) * NV4 + lane];
        m.x += p.x; m.y += p.y; m.z += p.z; m.w += p.w;
    }
    const float invN = 1.0f / NPTS;
    m.x *= invN; m.y *= invN; m.z *= invN; m.w *= invN;

    float d     = warpsum(dot4(m, m));
    float m0raw = __shfl_sync(0xffffffffu, m.x, 0);
    float neg   = fmaxf(2.f * m0raw * m0raw - d, 1e-8f);   // -linner(m,m)
    float inv   = rsqrtf(neg);
    float4 mean = make_float4(m.x * inv, m.y * inv, m.z * inv, m.w * inv);
    g_mean[b * NV4 + lane] = mean;

    float dmm = warpsum(dot4(mean, mean));
    float dbm = warpsum(dot4(beta4, mean));
    float dbb = warpsum(dot4(beta4, beta4));
    float mean0 = __shfl_sync(0xffffffffu, mean.x, 0);
    if (lane == 0) {
        float b0 = beta4.x;
        float* sc = g_sc + b * 16;
        sc[0] = mean0;
        sc[1] = 1.f / (1.f + mean0);
        sc[2] = dmm;
        sc[3] = dmm + 2.f * mean0 + 1.f;   // dot(mean+e0, mean+e0)
        sc[4] = dbm;
        sc[5] = dbm + b0;                  // dot(beta, mean+e0)
        sc[6] = b0;
        sc[7] = 1.f / (1.f + b0);
        sc[8] = dbb + 2.f * b0 + 1.f;      // dot(beta+e0, beta+e0)
    }
}

// ---------------- K3: per-point tangent scalars + var partials ----------------
__global__ __launch_bounds__(256)
void k3_tangent(const float* __restrict__ x, const float* __restrict__ beta) {
    const int blk = blockIdx.x, b = blk >> 4, sl = blk & 15;
    const int warp = threadIdx.x >> 5, lane = threadIdx.x & 31;
    const float4* __restrict__ xb = (const float4*)x + (size_t)b * NPTS * NV4;

    const float4 mean4 = g_mean[b * NV4 + lane];
    const float4 beta4 = ((const float4*)beta)[lane];
    const float* sc = g_sc + b * 16;
    const float mean0 = sc[0], i1m = sc[1], dmm = sc[2], emem = sc[3];
    const float dbm   = sc[4], dbe = sc[5];

    const int base = sl * PPS + warp * PPWARP;
    float4 my4 = make_float4(0.f, 0.f, 0.f, 0.f);
    float  myd = 0.f;
    float  nacc = 0.f;

    for (int k = 0; k < PPWARP; ++k) {
        float4 v = xb[(size_t)(base + k) * NV4 + lane];
        float dxx = dot4(v, v);
        float dxm = dot4(v, mean4);
        float dbx = dot4(v, beta4);
        warpsum3(dxx, dxm, dbx);
        float x0 = __shfl_sync(0xffffffffu, v.x, 0);

        float alpha = fmaxf(2.f * mean0 * x0 - dxm, 1.f + 1e-7f);
        float duu   = dxx - 2.f * alpha * dxm + alpha * alpha * dmm;  // dot(u,u)
        float u0    = x0 - alpha * mean0;
        float linuu = fmaxf(duu - 2.f * u0 * u0, 1e-8f);              // linner(u,u)
        float un    = sqrtf(linuu);
        float s     = acoshf(alpha) / un;
        float c     = s * u0 * i1m;
        float due   = dxm - alpha * dmm + u0;                         // dot(u, mean+e0)
        float t2    = fmaxf(s * s * duu - 2.f * s * c * due + c * c * emem, 0.f);
        float dbt   = s * (dbx - alpha * dbm) - c * dbe;              // dot(beta, x_T)
        nacc += sqrtf(t2);
        if (lane == k) { my4 = make_float4(s, s * alpha, c, t2); myd = dbt; }
    }
    const size_t o = (size_t)b * NPTS + base + lane;
    g_scr4[o] = my4;
    g_scrd[o] = myd;

    __shared__ float sv[8];
    if (lane == 0) sv[warp] = nacc;   // nacc is warp-uniform
    __syncthreads();
    if (threadIdx.x == 0) {
        float t = 0.f;
        #pragma unroll
        for (int i = 0; i < 8; ++i) t += sv[i];
        g_vpart[blk] = t;
    }
}

// ---------------- K4: scale, transport to beta, expmap, write ----------------
__global__ __launch_bounds__(256)
void k4_final(const float* __restrict__ x, const float* __restrict__ beta,
              const float* __restrict__ gamma, float* __restrict__ out) {
    const int blk = blockIdx.x, b = blk >> 4, sl = blk & 15;
    const int warp = threadIdx.x >> 5, lane = threadIdx.x & 31;
    const float4* __restrict__ xb = (const float4*)x + (size_t)b * NPTS * NV4;
    float4* __restrict__ ob       = (float4*)out + (size_t)b * NPTS * NV4;

    // per-batch gamma scale (redundant per thread; uniform loads)
    float vsum = 0.f;
    #pragma unroll
    for (int s = 0; s < NSL; ++s) vsum += g_vpart[b * NSL + s];
    const float var = vsum * (1.0f / NPTS);
    const float g   = gamma[0] / (var + 1e-5f);

    const float4 mean4 = g_mean[b * NV4 + lane];
    const float4 beta4 = ((const float4*)beta)[lane];
    const float* sc = g_sc + b * 16;
    const float b0 = sc[6], i1b = sc[7], nbb = sc[8];

    float4 em = mean4, be = beta4;
    if (lane == 0) { em.x += 1.f; be.x += 1.f; }

    const int base = sl * PPS + warp * PPWARP;
    for (int k = 0; k < PPWARP; ++k) {
        const int p = base + k;
        float4 v   = xb[(size_t)p * NV4 + lane];
        float4 A   = g_scr4[(size_t)b * NPTS + p];   // uniform broadcast load
        float  dbt = g_scrd[(size_t)b * NPTS + p];
        const float s = A.x, sa = A.y, c = A.z, t2 = A.w;

        // y = g * x_T  (x_T0 = 0 exactly after transport to origin)
        float4 y;
        y.x = g * (s * v.x - sa * mean4.x - c * em.x);
        y.y = g * (s * v.y - sa * mean4.y - c * em.y);
        y.z = g * (s * v.z - sa * mean4.z - c * em.z);
        y.w = g * (s * v.w - sa * mean4.w - c * em.w);

        const float gd = g * dbt;              // linner(beta, y) since y0 = 0
        const float pt = gd * i1b;

        float4 f;
        f.x = y.x + pt * be.x;
        f.y = y.y + pt * be.y;
        f.z = y.z + pt * be.z;
        f.w = y.w + pt * be.w;

        const float dff = g * g * t2 + 2.f * pt * gd + pt * pt * nbb;
        const float f0  = pt * (b0 + 1.f);
        const float lf  = fmaxf(dff - 2.f * f0 * f0, 1e-8f);
        const float nu  = sqrtf(lf);
        const float ch  = coshf(nu);
        const float sh  = sinhf(nu) / nu;

        float4 o;
        o.x = ch * beta4.x + sh * f.x;
        o.y = ch * beta4.y + sh * f.y;
        o.z = ch * beta4.z + sh * f.z;
        o.w = ch * beta4.w + sh * f.w;
        ob[(size_t)p * NV4 + lane] = o;
    }
}

extern "C" void kernel_launch(void* const* d_in, const int* in_sizes, int n_in,
                              void* d_out, int out_size) {
    const float* x     = (const float*)d_in[0];
    const float* beta  = (const float*)d_in[1];
    const float* gamma = (const float*)d_in[2];
    float* out = (float*)d_out;

    k1_sums   <<<NBATCH * NSL, 256>>>(x);
    k2_mean   <<<NBATCH, 32>>>(beta);
    k3_tangent<<<NBATCH * NSL, 256>>>(x, beta);
    k4_final  <<<NBATCH * NSL, 256>>>(x, beta, gamma, out);
}

// round 9
// speedup vs baseline: 1.9704x; 1.0800x over previous
#include <cuda_runtime.h>

#define NBATCH 64
#define NPTS   4096
#define NV4    32                  // 128 channels = 32 float4
#define NSL    16                  // slices per batch
#define PPS    (NPTS / NSL)        // 256 points per slice/CTA
#define PPWARP 32                  // points per warp (8 warps/CTA)

#define GB      32                 // batches per group-chain (64 MB of x)
#define NGROUPS (NBATCH / GB)      // 2

// scratch (device globals; no allocation)
__device__ float4 g_part [NBATCH * NSL * NV4];
__device__ float4 g_mean [NBATCH * NV4];
__device__ float  g_sc   [NBATCH * 16];
__device__ float4 g_scr4 [NBATCH * NPTS];        // {s, s*alpha, c, t2}
__device__ float  g_scrd [NBATCH * NPTS];        // dot(beta, x_T)
__device__ float  g_vpart[NBATCH * NSL];

__device__ __forceinline__ float dot4(float4 a, float4 b) {
    return a.x * b.x + a.y * b.y + a.z * b.z + a.w * b.w;
}
__device__ __forceinline__ float warpsum(float v) {
    #pragma unroll
    for (int o = 16; o > 0; o >>= 1) v += __shfl_xor_sync(0xffffffffu, v, o);
    return v;
}
__device__ __forceinline__ void warpsum3(float& a, float& b, float& c) {
    #pragma unroll
    for (int o = 16; o > 0; o >>= 1) {
        a += __shfl_xor_sync(0xffffffffu, a, o);
        b += __shfl_xor_sync(0xffffffffu, b, o);
        c += __shfl_xor_sync(0xffffffffu, c, o);
    }
}

// ---------------- K1: per-slice channel sums ----------------
__global__ __launch_bounds__(256)
void k1_sums(const float* __restrict__ x, int b0) {
    const int b = b0 + (blockIdx.x >> 4), sl = blockIdx.x & 15;
    const int warp = threadIdx.x >> 5, lane = threadIdx.x & 31;
    const float4* __restrict__ xb = (const float4*)x + (size_t)b * NPTS * NV4;
    const int base = sl * PPS + warp * PPWARP;

    float4 acc = make_float4(0.f, 0.f, 0.f, 0.f);
    #pragma unroll 4
    for (int k = 0; k < PPWARP; ++k) {
        float4 v = xb[(size_t)(base + k) * NV4 + lane];
        acc.x += v.x; acc.y += v.y; acc.z += v.z; acc.w += v.w;
    }
    __shared__ float4 sr[256];
    sr[threadIdx.x] = acc;
    __syncthreads();
    #pragma unroll
    for (int off = 128; off >= 32; off >>= 1) {
        if (threadIdx.x < off) {
            float4 a = sr[threadIdx.x], c = sr[threadIdx.x + off];
            a.x += c.x; a.y += c.y; a.z += c.z; a.w += c.w;
            sr[threadIdx.x] = a;
        }
        __syncthreads();
    }
    if (threadIdx.x < 32) g_part[(b * NSL + sl) * NV4 + lane] = sr[lane];
}

// ---------------- K2: mean + per-batch scalars ----------------
__global__ __launch_bounds__(32)
void k2_mean(const float* __restrict__ beta, int b0) {
    const int b = b0 + blockIdx.x, lane = threadIdx.x;
    const float4 beta4 = ((const float4*)beta)[lane];

    float4 m = make_float4(0.f, 0.f, 0.f, 0.f);
    for (int s = 0; s < NSL; ++s) {
        float4 p = g_part[(b * NSL + s) * NV4 + lane];
        m.x += p.x; m.y += p.y; m.z += p.z; m.w += p.w;
    }
    const float invN = 1.0f / NPTS;
    m.x *= invN; m.y *= invN; m.z *= invN; m.w *= invN;

    float d     = warpsum(dot4(m, m));
    float m0raw = __shfl_sync(0xffffffffu, m.x, 0);
    float neg   = fmaxf(2.f * m0raw * m0raw - d, 1e-8f);   // -linner(m,m)
    float inv   = rsqrtf(neg);
    float4 mean = make_float4(m.x * inv, m.y * inv, m.z * inv, m.w * inv);
    g_mean[b * NV4 + lane] = mean;

    float dmm = warpsum(dot4(mean, mean));
    float dbm = warpsum(dot4(beta4, mean));
    float dbb = warpsum(dot4(beta4, beta4));
    float mean0 = __shfl_sync(0xffffffffu, mean.x, 0);
    if (lane == 0) {
        float bb0 = beta4.x;
        float* sc = g_sc + b * 16;
        sc[0] = mean0;
        sc[1] = 1.f / (1.f + mean0);
        sc[2] = dmm;
        sc[3] = dmm + 2.f * mean0 + 1.f;   // dot(mean+e0, mean+e0)
        sc[4] = dbm;
        sc[5] = dbm + bb0;                 // dot(beta, mean+e0)
        sc[6] = bb0;
        sc[7] = 1.f / (1.f + bb0);
        sc[8] = dbb + 2.f * bb0 + 1.f;     // dot(beta+e0, beta+e0)
    }
}

// ---------------- K3: per-point tangent scalars + var partials ----------------
__global__ __launch_bounds__(256)
void k3_tangent(const float* __restrict__ x, const float* __restrict__ beta, int b0) {
    const int b = b0 + (blockIdx.x >> 4), sl = blockIdx.x & 15;
    const int warp = threadIdx.x >> 5, lane = threadIdx.x & 31;
    const float4* __restrict__ xb = (const float4*)x + (size_t)b * NPTS * NV4;

    const float4 mean4 = g_mean[b * NV4 + lane];
    const float4 beta4 = ((const float4*)beta)[lane];
    const float* sc = g_sc + b * 16;
    const float mean0 = sc[0], i1m = sc[1], dmm = sc[2], emem = sc[3];
    const float dbm   = sc[4], dbe = sc[5];

    const int base = sl * PPS + warp * PPWARP;
    float4 my4 = make_float4(0.f, 0.f, 0.f, 0.f);
    float  myd = 0.f;
    float  nacc = 0.f;

    #pragma unroll 2
    for (int k = 0; k < PPWARP; ++k) {
        float4 v = xb[(size_t)(base + k) * NV4 + lane];
        float dxx = dot4(v, v);
        float dxm = dot4(v, mean4);
        float dbx = dot4(v, beta4);
        warpsum3(dxx, dxm, dbx);
        float x0 = __shfl_sync(0xffffffffu, v.x, 0);

        float alpha = fmaxf(2.f * mean0 * x0 - dxm, 1.f + 1e-7f);
        float duu   = dxx - 2.f * alpha * dxm + alpha * alpha * dmm;  // dot(u,u)
        float u0    = x0 - alpha * mean0;
        float linuu = fmaxf(duu - 2.f * u0 * u0, 1e-8f);              // linner(u,u)
        float run   = rsqrtf(linuu);
        float s     = acoshf(alpha) * run;
        float c     = s * u0 * i1m;
        float due   = dxm - alpha * dmm + u0;                         // dot(u, mean+e0)
        float t2    = fmaxf(s * s * duu - 2.f * s * c * due + c * c * emem, 0.f);
        float dbt   = s * (dbx - alpha * dbm) - c * dbe;              // dot(beta, x_T)
        nacc += sqrtf(t2);
        if (lane == k) { my4 = make_float4(s, s * alpha, c, t2); myd = dbt; }
    }
    const size_t o = (size_t)b * NPTS + base + lane;
    g_scr4[o] = my4;
    g_scrd[o] = myd;

    __shared__ float sv[8];
    if (lane == 0) sv[warp] = nacc;   // nacc is warp-uniform
    __syncthreads();
    if (threadIdx.x == 0) {
        float t = 0.f;
        #pragma unroll
        for (int i = 0; i < 8; ++i) t += sv[i];
        g_vpart[b * NSL + sl] = t;
    }
}

// ---------------- K4: scale, transport to beta, expmap, write ----------------
__global__ __launch_bounds__(256)
void k4_final(const float* __restrict__ x, const float* __restrict__ beta,
              const float* __restrict__ gamma, float* __restrict__ out, int b0) {
    const int b = b0 + (blockIdx.x >> 4), sl = blockIdx.x & 15;
    const int warp = threadIdx.x >> 5, lane = threadIdx.x & 31;
    const float4* __restrict__ xb = (const float4*)x + (size_t)b * NPTS * NV4;
    float4* __restrict__ ob       = (float4*)out + (size_t)b * NPTS * NV4;

    float vsum = 0.f;
    #pragma unroll
    for (int s = 0; s < NSL; ++s) vsum += g_vpart[b * NSL + s];
    const float var = vsum * (1.0f / NPTS);
    const float g   = gamma[0] / (var + 1e-5f);

    const float4 mean4 = g_mean[b * NV4 + lane];
    const float4 beta4 = ((const float4*)beta)[lane];
    const float* sc = g_sc + b * 16;
    const float b0s = sc[6], i1b = sc[7], nbb = sc[8];

    float4 em = mean4, be = beta4;
    if (lane == 0) { em.x += 1.f; be.x += 1.f; }

    const int base = sl * PPS + warp * PPWARP;
    #pragma unroll 4
    for (int k = 0; k < PPWARP; ++k) {
        const int p = base + k;
        float4 v   = xb[(size_t)p * NV4 + lane];
        float4 A   = g_scr4[(size_t)b * NPTS + p];   // uniform broadcast load
        float  dbt = g_scrd[(size_t)b * NPTS + p];
        const float s = A.x, sa = A.y, c = A.z, t2 = A.w;

        // y = g * x_T  (x_T0 = 0 exactly after transport to origin)
        float4 y;
        y.x = g * (s * v.x - sa * mean4.x - c * em.x);
        y.y = g * (s * v.y - sa * mean4.y - c * em.y);
        y.z = g * (s * v.z - sa * mean4.z - c * em.z);
        y.w = g * (s * v.w - sa * mean4.w - c * em.w);

        const float gd = g * dbt;              // linner(beta, y) since y0 = 0
        const float pt = gd * i1b;

        float4 f;
        f.x = y.x + pt * be.x;
        f.y = y.y + pt * be.y;
        f.z = y.z + pt * be.z;
        f.w = y.w + pt * be.w;

        const float dff = g * g * t2 + 2.f * pt * gd + pt * pt * nbb;
        const float f0  = pt * (b0s + 1.f);
        const float lf  = fmaxf(dff - 2.f * f0 * f0, 1e-8f);
        const float rnu = rsqrtf(lf);
        const float nu  = lf * rnu;            // sqrt(lf)
        const float ex  = __expf(nu);
        const float ei  = __expf(-nu);
        const float ch  = 0.5f * (ex + ei);
        const float sh  = 0.5f * (ex - ei) * rnu;  // sinh(nu)/nu

        float4 o;
        o.x = ch * beta4.x + sh * f.x;
        o.y = ch * beta4.y + sh * f.y;
        o.z = ch * beta4.z + sh * f.z;
        o.w = ch * beta4.w + sh * f.w;
        // streaming store: don't let output displace x in L2
        __stcs(&ob[(size_t)p * NV4 + lane], o);
    }
}

extern "C" void kernel_launch(void* const* d_in, const int* in_sizes, int n_in,
                              void* d_out, int out_size) {
    const float* x     = (const float*)d_in[0];
    const float* beta  = (const float*)d_in[1];
    const float* gamma = (const float*)d_in[2];
    float* out = (float*)d_out;

    // Single-stream group chaining: each group of GB batches (64 MB of x)
    // runs k1->k2->k3->k4 back-to-back, so k3/k4 re-read the group's x while
    // it is still resident in the 126 MB L2. No streams/events (allocation
    // guard forbids creating them).
    for (int grp = 0; grp < NGROUPS; ++grp) {
        const int b0 = grp * GB;
        k1_sums   <<<GB * NSL, 256>>>(x, b0);
        k2_mean   <<<GB,       32 >>>(beta, b0);
        k3_tangent<<<GB * NSL, 256>>>(x, beta, b0);
        k4_final  <<<GB * NSL, 256>>>(x, beta, gamma, out, b0);
    }
}

// round 11
// speedup vs baseline: 2.1520x; 1.0922x over previous
#include <cuda_runtime.h>

#define NBATCH 64
#define NPTS   4096
#define NV4    32                  // 128 channels = 32 float4
#define NSL    32                  // slices per batch
#define PPS    (NPTS / NSL)        // 128 points per slice/CTA
#define PPWARP 16                  // points per warp (8 warps/CTA)

#define GB      32                 // batches per group-chain (64 MB of x)
#define NGROUPS (NBATCH / GB)      // 2

// scratch (device globals; no allocation)
__device__ float4 g_part [NBATCH * NSL * NV4];
__device__ float4 g_mean [NBATCH * NV4];
__device__ float  g_sc   [NBATCH * 16];
__device__ float4 g_scr4 [NBATCH * NPTS];        // {s, s*alpha, c, dbt*i1b}
__device__ float  g_scrq [NBATCH * NPTS];        // sqrt(t2 + dbt^2 * K)
__device__ float  g_vpart[NBATCH * NSL];

__device__ __forceinline__ float dot4(float4 a, float4 b) {
    return a.x * b.x + a.y * b.y + a.z * b.z + a.w * b.w;
}
__device__ __forceinline__ float warpsum(float v) {
    #pragma unroll
    for (int o = 16; o > 0; o >>= 1) v += __shfl_xor_sync(0xffffffffu, v, o);
    return v;
}
__device__ __forceinline__ void warpsum3(float& a, float& b, float& c) {
    #pragma unroll
    for (int o = 16; o > 0; o >>= 1) {
        a += __shfl_xor_sync(0xffffffffu, a, o);
        b += __shfl_xor_sync(0xffffffffu, b, o);
        c += __shfl_xor_sync(0xffffffffu, c, o);
    }
}

// ---------------- K1: per-slice channel sums ----------------
__global__ __launch_bounds__(256)
void k1_sums(const float* __restrict__ x, int b0) {
    const int b = b0 + (blockIdx.x >> 5), sl = blockIdx.x & 31;
    const int warp = threadIdx.x >> 5, lane = threadIdx.x & 31;
    const float4* __restrict__ xb = (const float4*)x + (size_t)b * NPTS * NV4;
    const int base = sl * PPS + warp * PPWARP;

    float4 acc = make_float4(0.f, 0.f, 0.f, 0.f);
    #pragma unroll 4
    for (int k = 0; k < PPWARP; ++k) {
        float4 v = xb[(size_t)(base + k) * NV4 + lane];
        acc.x += v.x; acc.y += v.y; acc.z += v.z; acc.w += v.w;
    }
    __shared__ float4 sr[256];
    sr[threadIdx.x] = acc;
    __syncthreads();
    #pragma unroll
    for (int off = 128; off >= 32; off >>= 1) {
        if (threadIdx.x < off) {
            float4 a = sr[threadIdx.x], c = sr[threadIdx.x + off];
            a.x += c.x; a.y += c.y; a.z += c.z; a.w += c.w;
            sr[threadIdx.x] = a;
        }
        __syncthreads();
    }
    if (threadIdx.x < 32) g_part[(b * NSL + sl) * NV4 + lane] = sr[lane];
}

// ---------------- K2: mean + per-batch scalars ----------------
__global__ __launch_bounds__(32)
void k2_mean(const float* __restrict__ beta, int b0) {
    const int b = b0 + blockIdx.x, lane = threadIdx.x;
    const float4 beta4 = ((const float4*)beta)[lane];

    float4 m = make_float4(0.f, 0.f, 0.f, 0.f);
    for (int s = 0; s < NSL; ++s) {
        float4 p = g_part[(b * NSL + s) * NV4 + lane];
        m.x += p.x; m.y += p.y; m.z += p.z; m.w += p.w;
    }
    const float invN = 1.0f / NPTS;
    m.x *= invN; m.y *= invN; m.z *= invN; m.w *= invN;

    float d     = warpsum(dot4(m, m));
    float m0raw = __shfl_sync(0xffffffffu, m.x, 0);
    float neg   = fmaxf(2.f * m0raw * m0raw - d, 1e-8f);   // -linner(m,m)
    float inv   = rsqrtf(neg);
    float4 mean = make_float4(m.x * inv, m.y * inv, m.z * inv, m.w * inv);
    g_mean[b * NV4 + lane] = mean;

    float dmm = warpsum(dot4(mean, mean));
    float dbm = warpsum(dot4(beta4, mean));
    float dbb = warpsum(dot4(beta4, beta4));
    float mean0 = __shfl_sync(0xffffffffu, mean.x, 0);
    if (lane == 0) {
        float bb0 = beta4.x;
        float i1b = 1.f / (1.f + bb0);
        float nbb = dbb + 2.f * bb0 + 1.f;     // dot(beta+e0, beta+e0)
        float* sc = g_sc + b * 16;
        sc[0] = mean0;
        sc[1] = 1.f / (1.f + mean0);
        sc[2] = dmm;
        sc[3] = dmm + 2.f * mean0 + 1.f;   // dot(mean+e0, mean+e0)
        sc[4] = dbm;
        sc[5] = dbm + bb0;                 // dot(beta, mean+e0)
        sc[6] = bb0;
        sc[7] = i1b;
        sc[8] = nbb;
        // K such that linner(f,f) = g^2 * (t2 + dbt^2 * K)
        float bp1 = bb0 + 1.f;
        sc[9] = 2.f * i1b + i1b * i1b * (nbb - 2.f * bp1 * bp1);
    }
}

// ---------------- K3: per-point tangent scalars + var partials ----------------
__global__ __launch_bounds__(256)
void k3_tangent(const float* __restrict__ x, const float* __restrict__ beta, int b0) {
    const int b = b0 + (blockIdx.x >> 5), sl = blockIdx.x & 31;
    const int warp = threadIdx.x >> 5, lane = threadIdx.x & 31;
    const float4* __restrict__ xb = (const float4*)x + (size_t)b * NPTS * NV4;

    const float4 mean4 = g_mean[b * NV4 + lane];
    const float4 beta4 = ((const float4*)beta)[lane];
    const float* sc = g_sc + b * 16;
    const float mean0 = sc[0], i1m = sc[1], dmm = sc[2], emem = sc[3];
    const float dbm   = sc[4], dbe = sc[5], i1b = sc[7], Kb = sc[9];

    const int base = sl * PPS + warp * PPWARP;
    float4 my4 = make_float4(0.f, 0.f, 0.f, 0.f);
    float  myq = 0.f;
    float  nacc = 0.f;

    #pragma unroll 2
    for (int k = 0; k < PPWARP; ++k) {
        float4 v = xb[(size_t)(base + k) * NV4 + lane];
        float dxx = dot4(v, v);
        float dxm = dot4(v, mean4);
        float dbx = dot4(v, beta4);
        warpsum3(dxx, dxm, dbx);
        float x0 = __shfl_sync(0xffffffffu, v.x, 0);

        float alpha = fmaxf(2.f * mean0 * x0 - dxm, 1.f + 1e-7f);
        float duu   = dxx - 2.f * alpha * dxm + alpha * alpha * dmm;  // dot(u,u)
        float u0    = x0 - alpha * mean0;
        float linuu = fmaxf(duu - 2.f * u0 * u0, 1e-8f);              // linner(u,u)
        float run   = rsqrtf(linuu);
        float ac    = __logf(alpha + sqrtf(fmaf(alpha, alpha, -1.f))); // acosh
        float s     = ac * run;
        float c     = s * u0 * i1m;
        float due   = dxm - alpha * dmm + u0;                         // dot(u, mean+e0)
        float t2    = fmaxf(s * s * duu - 2.f * s * c * due + c * c * emem, 0.f);
        float dbt   = s * (dbx - alpha * dbm) - c * dbe;              // dot(beta, x_T)
        float q     = fmaxf(t2 + dbt * dbt * Kb, 0.f);
        nacc += sqrtf(t2);
        if (lane == k) { my4 = make_float4(s, s * alpha, c, dbt * i1b); myq = sqrtf(q); }
    }
    if (lane < PPWARP) {
        const size_t o = (size_t)b * NPTS + base + lane;
        g_scr4[o] = my4;
        g_scrq[o] = myq;
    }

    __shared__ float sv[8];
    if (lane == 0) sv[warp] = nacc;   // nacc is warp-uniform
    __syncthreads();
    if (threadIdx.x == 0) {
        float t = 0.f;
        #pragma unroll
        for (int i = 0; i < 8; ++i) t += sv[i];
        g_vpart[b * NSL + sl] = t;
    }
}

// ---------------- K4: scale, transport to beta, expmap, write ----------------
__global__ __launch_bounds__(256)
void k4_final(const float* __restrict__ x, const float* __restrict__ beta,
              const float* __restrict__ gamma, float* __restrict__ out, int b0) {
    const int b = b0 + (blockIdx.x >> 5), sl = blockIdx.x & 31;
    const int warp = threadIdx.x >> 5, lane = threadIdx.x & 31;
    const float4* __restrict__ xb = (const float4*)x + (size_t)b * NPTS * NV4;
    float4* __restrict__ ob       = (float4*)out + (size_t)b * NPTS * NV4;

    float vsum = 0.f;
    #pragma unroll
    for (int s = 0; s < NSL; ++s) vsum += g_vpart[b * NSL + s];
    const float var = vsum * (1.0f / NPTS);
    const float g   = gamma[0] / (var + 1e-5f);

    const float4 mean4 = g_mean[b * NV4 + lane];
    const float4 beta4 = ((const float4*)beta)[lane];

    float4 em = mean4, be = beta4;
    if (lane == 0) { em.x += 1.f; be.x += 1.f; }

    const int base = sl * PPS + warp * PPWARP;
    #pragma unroll 4
    for (int k = 0; k < PPWARP; ++k) {
        const int p = base + k;
        float4 v  = __ldcs(&xb[(size_t)p * NV4 + lane]);   // last use of x: evict-first
        float4 A  = g_scr4[(size_t)b * NPTS + p];          // uniform broadcast load
        float  sq = g_scrq[(size_t)b * NPTS + p];
        const float s = A.x, sa = A.y, c = A.z, dbi = A.w; // dbi = dbt * i1b

        // y = g * x_T  (x_T0 = 0 exactly after transport to origin)
        float4 y;
        y.x = g * (s * v.x - sa * mean4.x - c * em.x);
        y.y = g * (s * v.y - sa * mean4.y - c * em.y);
        y.z = g * (s * v.z - sa * mean4.z - c * em.z);
        y.w = g * (s * v.w - sa * mean4.w - c * em.w);

        const float pt = g * dbi;              // linner(beta,y)/(1+b0)

        float4 f;
        f.x = y.x + pt * be.x;
        f.y = y.y + pt * be.y;
        f.z = y.z + pt * be.z;
        f.w = y.w + pt * be.w;

        // nu = sqrt(max(linner(f,f),1e-8)) = max(g*sq, 1e-4)
        const float nu  = fmaxf(g * sq, 1e-4f);
        const float ex  = __expf(nu);
        const float ei  = __expf(-nu);
        const float ch  = 0.5f * (ex + ei);
        const float sh  = 0.5f * (ex - ei) * __fdividef(1.f, nu);  // sinh(nu)/nu

        float4 o;
        o.x = ch * beta4.x + sh * f.x;
        o.y = ch * beta4.y + sh * f.y;
        o.z = ch * beta4.z + sh * f.z;
        o.w = ch * beta4.w + sh * f.w;
        __stcs(&ob[(size_t)p * NV4 + lane], o);  // streaming store
    }
}

extern "C" void kernel_launch(void* const* d_in, const int* in_sizes, int n_in,
                              void* d_out, int out_size) {
    const float* x     = (const float*)d_in[0];
    const float* beta  = (const float*)d_in[1];
    const float* gamma = (const float*)d_in[2];
    float* out = (float*)d_out;

    // Single-stream group chaining: each group of GB batches (64 MB of x)
    // runs k1->k2->k3->k4 back-to-back so k3/k4 re-read the group's x from L2.
    for (int grp = 0; grp < NGROUPS; ++grp) {
        const int b0 = grp * GB;
        k1_sums   <<<GB * NSL, 256>>>(x, b0);
        k2_mean   <<<GB,       32 >>>(beta, b0);
        k3_tangent<<<GB * NSL, 256>>>(x, beta, b0);
        k4_final  <<<GB * NSL, 256>>>(x, beta, gamma, out, b0);
    }
}